// round 1
// baseline (speedup 1.0000x reference)
#include <cuda_runtime.h>
#include <cuda_bf16.h>
#include <math.h>

// Problem constants
#define BSZ 4
#define SEQ 2048
#define DIM 512
#define NHEAD 8
#define NLAYER 4
#define FFDIM 2048
#define HDIM 64
#define HALFHD 32
#define EPSV 1e-6f
#define ALPHAV 0.5f
#define LOG_ROPE_BASE 9.210340371976184   // ln(10000)

#define BT (BSZ * SEQ)                    // 8192

// ---------------- scratch layout (single static device buffer) ----------------
constexpr size_t NX    = (size_t)BT * DIM;        // 4,194,304
constexpr size_t NHID  = (size_t)BT * FFDIM;      // 16,777,216
constexpr size_t NS    = (size_t)BSZ * NHEAD * SEQ * SEQ; // 134,217,728
constexpr size_t NSEGS = (size_t)BSZ * (SEQ + 1) * DIM;   // 4,196,352
constexpr size_t NSEGC = (size_t)BSZ * (SEQ + 1);         // 8,196
constexpr size_t NROPE = (size_t)SEQ * HALFHD;            // 65,536

constexpr size_t OFF_X    = 0;
constexpr size_t OFF_Y    = OFF_X  + NX;
constexpr size_t OFF_XN   = OFF_Y  + NX;
constexpr size_t OFF_Q    = OFF_XN + NX;
constexpr size_t OFF_K    = OFF_Q  + NX;
constexpr size_t OFF_V    = OFF_K  + NX;
constexpr size_t OFF_QP   = OFF_V  + NX;
constexpr size_t OFF_KP   = OFF_QP + NX;
constexpr size_t OFF_VP   = OFF_KP + NX;
constexpr size_t OFF_OP   = OFF_VP + NX;
constexpr size_t OFF_OC   = OFF_OP + NX;
constexpr size_t OFF_HF   = OFF_OC + NX;
constexpr size_t OFF_H1   = OFF_HF + NX;
constexpr size_t OFF_H3   = OFF_H1 + NHID;
constexpr size_t OFF_G    = OFF_H3 + NHID;
constexpr size_t OFF_S    = OFF_G  + NHID;
constexpr size_t OFF_SSUM = OFF_S  + NS;
constexpr size_t OFF_SCNT = OFF_SSUM + NSEGS;
constexpr size_t OFF_COS  = OFF_SCNT + NSEGC;
constexpr size_t OFF_SIN  = OFF_COS + NROPE;
constexpr size_t TOTALF   = OFF_SIN + NROPE;

__device__ float g_buf[TOTALF];
__device__ int   g_seg[BT];

// ---------------- helpers ----------------
__device__ __forceinline__ bool is_sep(int c) {
    switch (c) {
        case 9: case 10: case 13: case 32: case 33: case 34: case 35: case 36:
        case 37: case 38: case 39: case 40: case 41: case 42: case 43: case 44:
        case 45: case 46: case 47: case 58: case 59: case 60: case 61: case 62:
        case 63: case 64: case 91: case 92: case 93: case 94: case 123:
        case 124: case 125: case 126:
            return true;
        default:
            return false;
    }
}

// ---------------- small kernels ----------------
__global__ void embed_kernel(const int* __restrict__ tokens,
                             const float* __restrict__ embed,
                             float* __restrict__ x) {
    int m = blockIdx.x;
    int tok = tokens[m];
    tok = min(max(tok, 0), 255);
    reinterpret_cast<float4*>(x + (size_t)m * DIM)[threadIdx.x] =
        reinterpret_cast<const float4*>(embed + (size_t)tok * DIM)[threadIdx.x];
}

__global__ void rmsnorm_kernel(const float* __restrict__ x,
                               const float* __restrict__ w,
                               float* __restrict__ o) {
    int row = blockIdx.x;
    const float4 v = reinterpret_cast<const float4*>(x + (size_t)row * DIM)[threadIdx.x];
    float ss = v.x * v.x + v.y * v.y + v.z * v.z + v.w * v.w;
    for (int s = 16; s; s >>= 1) ss += __shfl_xor_sync(0xffffffffu, ss, s);
    __shared__ float red[4];
    int lane = threadIdx.x & 31, wp = threadIdx.x >> 5;
    if (!lane) red[wp] = ss;
    __syncthreads();
    ss = red[0] + red[1] + red[2] + red[3];
    float rs = rsqrtf(ss * (1.0f / DIM) + EPSV);
    float4 wv = reinterpret_cast<const float4*>(w)[threadIdx.x];
    float4 r = make_float4(v.x * rs * wv.x, v.y * rs * wv.y,
                           v.z * rs * wv.z, v.w * rs * wv.w);
    reinterpret_cast<float4*>(o + (size_t)row * DIM)[threadIdx.x] = r;
}

__global__ void rope_table_kernel(float* __restrict__ cosT, float* __restrict__ sinT) {
    int idx = blockIdx.x * blockDim.x + threadIdx.x;
    if (idx >= SEQ * HALFHD) return;
    int t = idx / HALFHD, i = idx % HALFHD;
    double inv = exp(-(double)i * (LOG_ROPE_BASE / (double)HALFHD));
    double ang = (double)t * inv;
    double s, c;
    sincos(ang, &s, &c);
    cosT[idx] = (float)c;
    sinT[idx] = (float)s;
}

// pack q,k,v:  [B,T,H*DH] -> [B,H,T,DH]; apply rope to q (with 1/sqrt(DH) scale) and k
__global__ void pack_rope_kernel(const float* __restrict__ qr,
                                 const float* __restrict__ kr,
                                 const float* __restrict__ vr,
                                 const float* __restrict__ cosT,
                                 const float* __restrict__ sinT,
                                 float* __restrict__ qp,
                                 float* __restrict__ kp,
                                 float* __restrict__ vp) {
    int gid = blockIdx.x * blockDim.x + threadIdx.x;
    if (gid >= BSZ * NHEAD * SEQ * HALFHD) return;
    int i = gid % HALFHD;
    int t = (gid / HALFHD) % SEQ;
    int h = (gid / (HALFHD * SEQ)) % NHEAD;
    int b = gid / (HALFHD * SEQ * NHEAD);
    size_t src = ((size_t)b * SEQ + t) * DIM + h * HDIM + 2 * i;
    size_t dst = (((size_t)(b * NHEAD + h)) * SEQ + t) * HDIM + 2 * i;
    float c = cosT[t * HALFHD + i];
    float s = sinT[t * HALFHD + i];
    float2 q2 = *reinterpret_cast<const float2*>(qr + src);
    float2 k2 = *reinterpret_cast<const float2*>(kr + src);
    float2 v2 = *reinterpret_cast<const float2*>(vr + src);
    const float qs = 0.125f; // 1/sqrt(64)
    *reinterpret_cast<float2*>(qp + dst) =
        make_float2((q2.x * c - q2.y * s) * qs, (q2.x * s + q2.y * c) * qs);
    *reinterpret_cast<float2*>(kp + dst) =
        make_float2(k2.x * c - k2.y * s, k2.x * s + k2.y * c);
    *reinterpret_cast<float2*>(vp + dst) = v2;
}

__global__ void softmax_kernel(float* __restrict__ S) {
    constexpr int NTH = 256, PT = SEQ / NTH;
    float* row = S + (size_t)blockIdx.x * SEQ;
    float v[PT];
    float mx = -1e30f;
#pragma unroll
    for (int j = 0; j < PT; j++) {
        v[j] = row[threadIdx.x + j * NTH];
        mx = fmaxf(mx, v[j]);
    }
    __shared__ float red[8];
    int lane = threadIdx.x & 31, wp = threadIdx.x >> 5;
    for (int s = 16; s; s >>= 1) mx = fmaxf(mx, __shfl_xor_sync(0xffffffffu, mx, s));
    if (!lane) red[wp] = mx;
    __syncthreads();
    mx = red[0];
#pragma unroll
    for (int i = 1; i < 8; i++) mx = fmaxf(mx, red[i]);
    float sum = 0.f;
#pragma unroll
    for (int j = 0; j < PT; j++) {
        v[j] = __expf(v[j] - mx);
        sum += v[j];
    }
    for (int s = 16; s; s >>= 1) sum += __shfl_xor_sync(0xffffffffu, sum, s);
    __syncthreads();
    if (!lane) red[wp] = sum;
    __syncthreads();
    sum = red[0];
#pragma unroll
    for (int i = 1; i < 8; i++) sum += red[i];
    float inv = 1.0f / sum;
#pragma unroll
    for (int j = 0; j < PT; j++) row[threadIdx.x + j * NTH] = v[j] * inv;
}

// [B,H,T,DH] -> [B,T,H*DH]
__global__ void unpack_o_kernel(const float* __restrict__ op, float* __restrict__ oc) {
    int m = blockIdx.x;
    int b = m / SEQ, t = m % SEQ;
    int c = threadIdx.x * 4;
    int h = c / HDIM, d = c % HDIM;
    float4 v = *reinterpret_cast<const float4*>(
        op + (((size_t)(b * NHEAD + h)) * SEQ + t) * HDIM + d);
    *reinterpret_cast<float4*>(oc + (size_t)m * DIM + c) = v;
}

__global__ void swiglu_kernel(const float* __restrict__ h1,
                              const float* __restrict__ h3,
                              float* __restrict__ g, size_t n) {
    size_t i = (size_t)blockIdx.x * blockDim.x + threadIdx.x;
    if (i < n) {
        float a = h1[i];
        float s = a / (1.0f + __expf(-a));
        g[i] = s * h3[i];
    }
}

__global__ void zero_kernel(float* __restrict__ p, size_t n) {
    size_t i = (size_t)blockIdx.x * blockDim.x + threadIdx.x;
    size_t stride = (size_t)gridDim.x * blockDim.x;
    for (; i < n; i += stride) p[i] = 0.0f;
}

// per-batch inclusive cumsum of separator flags -> segment ids
__global__ void segscan_kernel(const int* __restrict__ tokens, int* __restrict__ seg) {
    int b = blockIdx.x;
    constexpr int PT = SEQ / 256;
    int flags[PT];
    int s = 0;
#pragma unroll
    for (int j = 0; j < PT; j++) {
        int tok = tokens[b * SEQ + threadIdx.x * PT + j];
        tok = min(max(tok, 0), 255);
        flags[j] = is_sep(tok) ? 1 : 0;
        s += flags[j];
    }
    __shared__ int wsum[8];
    int lane = threadIdx.x & 31, wp = threadIdx.x >> 5;
    int ps = s;
    for (int o = 1; o < 32; o <<= 1) {
        int v = __shfl_up_sync(0xffffffffu, ps, o);
        if (lane >= o) ps += v;
    }
    if (lane == 31) wsum[wp] = ps;
    __syncthreads();
    int woff = 0;
    for (int i = 0; i < wp; i++) woff += wsum[i];
    int run = ps - s + woff; // exclusive prefix
#pragma unroll
    for (int j = 0; j < PT; j++) {
        run += flags[j];
        seg[b * SEQ + threadIdx.x * PT + j] = run + b * (SEQ + 1);
    }
}

__global__ void segsum_kernel(const float* __restrict__ h, const int* __restrict__ seg,
                              float* __restrict__ ssum, float* __restrict__ scnt) {
    int m = blockIdx.x;
    int s = seg[m];
    float4 v = reinterpret_cast<const float4*>(h + (size_t)m * DIM)[threadIdx.x];
    float* base = ssum + (size_t)s * DIM + threadIdx.x * 4;
    atomicAdd(base + 0, v.x);
    atomicAdd(base + 1, v.y);
    atomicAdd(base + 2, v.z);
    atomicAdd(base + 3, v.w);
    if (threadIdx.x == 0) atomicAdd(scnt + s, 1.0f);
}

__global__ void pool_kernel(const float* __restrict__ h, const int* __restrict__ seg,
                            const float* __restrict__ ssum, const float* __restrict__ scnt,
                            float* __restrict__ out) {
    int m = blockIdx.x;
    int s = seg[m];
    float inv = 1.0f / fmaxf(scnt[s], 1.0f);
    float4 v = reinterpret_cast<const float4*>(h + (size_t)m * DIM)[threadIdx.x];
    float4 sm = reinterpret_cast<const float4*>(ssum + (size_t)s * DIM)[threadIdx.x];
    float4 r = make_float4(ALPHAV * v.x + (1.0f - ALPHAV) * sm.x * inv,
                           ALPHAV * v.y + (1.0f - ALPHAV) * sm.y * inv,
                           ALPHAV * v.z + (1.0f - ALPHAV) * sm.z * inv,
                           ALPHAV * v.w + (1.0f - ALPHAV) * sm.w * inv);
    reinterpret_cast<float4*>(out + (size_t)m * DIM)[threadIdx.x] = r;
}

// ---------------- GEMM ----------------
// C[M,N] = A[M,K] @ op(B) (+R).  BisNT: B is [N,K] row-major (NT).  else: B is [K,N] (NN).
// All dims divide tile sizes (guaranteed by call sites). Batched via blockIdx.z.
template <int BM, int BN, int BK, int TM, int TN, bool BisNT>
__global__ void __launch_bounds__(256)
gemm_kernel(const float* __restrict__ A, const float* __restrict__ B,
            float* __restrict__ C, const float* __restrict__ R,
            int M, int N, int K, size_t sA, size_t sB, size_t sC) {
    constexpr int TX = BN / TN;
    constexpr int TY = BM / TM;
    constexpr int NTH = TX * TY;
    static_assert(NTH == 256, "block must be 256 threads");
    static_assert(TM % 4 == 0 && TN % 4 == 0, "frag vec4");

    __shared__ float As[BK][BM];
    __shared__ float Bs[BK][BN];

    const float* Ab = A + (size_t)blockIdx.z * sA;
    const float* Bb = B + (size_t)blockIdx.z * sB;

    const int bm = blockIdx.y * BM;
    const int bn = blockIdx.x * BN;
    const int tid = threadIdx.x;
    const int tx = tid % TX, ty = tid / TX;

    float acc[TM][TN] = {};

    for (int k0 = 0; k0 < K; k0 += BK) {
        // A tile: BM x BK
        for (int i = tid; i < BM * BK / 4; i += NTH) {
            int r = i / (BK / 4);
            int c = (i % (BK / 4)) * 4;
            float4 v = *reinterpret_cast<const float4*>(Ab + (size_t)(bm + r) * K + k0 + c);
            As[c + 0][r] = v.x;
            As[c + 1][r] = v.y;
            As[c + 2][r] = v.z;
            As[c + 3][r] = v.w;
        }
        if (BisNT) {
            for (int i = tid; i < BN * BK / 4; i += NTH) {
                int r = i / (BK / 4);
                int c = (i % (BK / 4)) * 4;
                float4 v = *reinterpret_cast<const float4*>(Bb + (size_t)(bn + r) * K + k0 + c);
                Bs[c + 0][r] = v.x;
                Bs[c + 1][r] = v.y;
                Bs[c + 2][r] = v.z;
                Bs[c + 3][r] = v.w;
            }
        } else {
            for (int i = tid; i < BN * BK / 4; i += NTH) {
                int r = i / (BN / 4);
                int c = (i % (BN / 4)) * 4;
                float4 v = *reinterpret_cast<const float4*>(Bb + (size_t)(k0 + r) * N + bn + c);
                *reinterpret_cast<float4*>(&Bs[r][c]) = v;
            }
        }
        __syncthreads();
#pragma unroll
        for (int kk = 0; kk < BK; kk++) {
            float ar[TM], br[TN];
#pragma unroll
            for (int i = 0; i < TM; i += 4)
                *reinterpret_cast<float4*>(&ar[i]) =
                    *reinterpret_cast<const float4*>(&As[kk][ty * TM + i]);
#pragma unroll
            for (int j = 0; j < TN; j += 4)
                *reinterpret_cast<float4*>(&br[j]) =
                    *reinterpret_cast<const float4*>(&Bs[kk][tx * TN + j]);
#pragma unroll
            for (int i = 0; i < TM; i++)
#pragma unroll
                for (int j = 0; j < TN; j++)
                    acc[i][j] = fmaf(ar[i], br[j], acc[i][j]);
        }
        __syncthreads();
    }

    float* Cb = C + (size_t)blockIdx.z * sC;
    const float* Rb = R ? R + (size_t)blockIdx.z * sC : nullptr;
#pragma unroll
    for (int i = 0; i < TM; i++) {
        size_t o = (size_t)(bm + ty * TM + i) * N + bn + tx * TN;
#pragma unroll
        for (int j = 0; j < TN; j += 4) {
            float4 v = make_float4(acc[i][j], acc[i][j + 1], acc[i][j + 2], acc[i][j + 3]);
            if (Rb) {
                float4 r = *reinterpret_cast<const float4*>(Rb + o + j);
                v.x += r.x; v.y += r.y; v.z += r.z; v.w += r.w;
            }
            *reinterpret_cast<float4*>(Cb + o + j) = v;
        }
    }
}

// ---------------- host ----------------
extern "C" void kernel_launch(void* const* d_in, const int* in_sizes, int n_in,
                              void* d_out, int out_size) {
    const int*   tokens       = (const int*)d_in[0];
    const float* embed        = (const float*)d_in[1];
    const float* attn_norm_w  = (const float*)d_in[2];
    const float* wq           = (const float*)d_in[3];
    const float* wk           = (const float*)d_in[4];
    const float* wv           = (const float*)d_in[5];
    const float* wo           = (const float*)d_in[6];
    const float* ffn_norm_w   = (const float*)d_in[7];
    const float* w1           = (const float*)d_in[8];
    const float* w2           = (const float*)d_in[9];
    const float* w3           = (const float*)d_in[10];
    const float* final_norm_w = (const float*)d_in[11];
    float* out = (float*)d_out;

    float* buf = nullptr;
    cudaGetSymbolAddress((void**)&buf, g_buf);
    int* seg = nullptr;
    cudaGetSymbolAddress((void**)&seg, g_seg);

    float* x    = buf + OFF_X;
    float* y    = buf + OFF_Y;
    float* xn   = buf + OFF_XN;
    float* qr   = buf + OFF_Q;
    float* kr   = buf + OFF_K;
    float* vr   = buf + OFF_V;
    float* qp   = buf + OFF_QP;
    float* kp   = buf + OFF_KP;
    float* vp   = buf + OFF_VP;
    float* op   = buf + OFF_OP;
    float* oc   = buf + OFF_OC;
    float* hf   = buf + OFF_HF;
    float* h1   = buf + OFF_H1;
    float* h3   = buf + OFF_H3;
    float* gg   = buf + OFF_G;
    float* S    = buf + OFF_S;
    float* ssum = buf + OFF_SSUM;
    float* scnt = buf + OFF_SCNT;
    float* cosT = buf + OFF_COS;
    float* sinT = buf + OFF_SIN;

    embed_kernel<<<BT, 128>>>(tokens, embed, x);
    rope_table_kernel<<<(SEQ * HALFHD + 255) / 256, 256>>>(cosT, sinT);

    const size_t strQK = (size_t)SEQ * HDIM;   // per (b,h) q/k/v stride
    const size_t strS  = (size_t)SEQ * SEQ;    // per (b,h) scores stride

    for (int l = 0; l < NLAYER; l++) {
        const float* wq_l = wq + (size_t)l * DIM * DIM;
        const float* wk_l = wk + (size_t)l * DIM * DIM;
        const float* wv_l = wv + (size_t)l * DIM * DIM;
        const float* wo_l = wo + (size_t)l * DIM * DIM;
        const float* w1_l = w1 + (size_t)l * FFDIM * DIM;
        const float* w2_l = w2 + (size_t)l * DIM * FFDIM;
        const float* w3_l = w3 + (size_t)l * FFDIM * DIM;

        // attn pre-norm
        rmsnorm_kernel<<<BT, 128>>>(x, attn_norm_w + (size_t)l * DIM, xn);

        // QKV projections: [8192,512] = [8192,512] @ [512,512]^T
        dim3 gproj(DIM / 128, BT / 128, 1);
        gemm_kernel<128, 128, 16, 16, 4, true><<<gproj, 256>>>(
            xn, wq_l, qr, nullptr, BT, DIM, DIM, 0, 0, 0);
        gemm_kernel<128, 128, 16, 16, 4, true><<<gproj, 256>>>(
            xn, wk_l, kr, nullptr, BT, DIM, DIM, 0, 0, 0);
        gemm_kernel<128, 128, 16, 16, 4, true><<<gproj, 256>>>(
            xn, wv_l, vr, nullptr, BT, DIM, DIM, 0, 0, 0);

        // pack to [B,H,T,DH] + RoPE (+ q scale)
        pack_rope_kernel<<<(BSZ * NHEAD * SEQ * HALFHD + 255) / 256, 256>>>(
            qr, kr, vr, cosT, sinT, qp, kp, vp);

        // scores: per (b,h) [2048,2048] = Q @ K^T
        dim3 gs(SEQ / 128, SEQ / 128, BSZ * NHEAD);
        gemm_kernel<128, 128, 16, 16, 4, true><<<gs, 256>>>(
            qp, kp, S, nullptr, SEQ, SEQ, HDIM, strQK, strQK, strS);

        softmax_kernel<<<BSZ * NHEAD * SEQ, 256>>>(S);

        // O = P @ V : per (b,h) [2048,64] = [2048,2048] @ [2048,64]
        dim3 gpv(HDIM / 64, SEQ / 128, BSZ * NHEAD);
        gemm_kernel<128, 64, 16, 8, 4, false><<<gpv, 256>>>(
            S, vp, op, nullptr, SEQ, HDIM, SEQ, strS, strQK, strQK);

        unpack_o_kernel<<<BT, 128>>>(op, oc);

        // y = x + O @ Wo^T
        gemm_kernel<128, 128, 16, 16, 4, true><<<gproj, 256>>>(
            oc, wo_l, y, x, BT, DIM, DIM, 0, 0, 0);

        // ffn pre-norm on y
        rmsnorm_kernel<<<BT, 128>>>(y, ffn_norm_w + (size_t)l * DIM, xn);

        dim3 gff(FFDIM / 128, BT / 128, 1);
        gemm_kernel<128, 128, 16, 16, 4, true><<<gff, 256>>>(
            xn, w1_l, h1, nullptr, BT, FFDIM, DIM, 0, 0, 0);
        gemm_kernel<128, 128, 16, 16, 4, true><<<gff, 256>>>(
            xn, w3_l, h3, nullptr, BT, FFDIM, DIM, 0, 0, 0);

        swiglu_kernel<<<(int)((NHID + 255) / 256), 256>>>(h1, h3, gg, NHID);

        // x = y + g @ W2^T   (K = 2048)
        gemm_kernel<128, 128, 16, 16, 4, true><<<gproj, 256>>>(
            gg, w2_l, x, y, BT, DIM, FFDIM, 0, 0, 0);
    }

    // final norm
    rmsnorm_kernel<<<BT, 128>>>(x, final_norm_w, hf);

    // segment pooling
    segscan_kernel<<<BSZ, 256>>>(tokens, seg);
    zero_kernel<<<4096, 256>>>(ssum, NSEGS + NSEGC);
    segsum_kernel<<<BT, 128>>>(hf, seg, ssum, scnt);
    pool_kernel<<<BT, 128>>>(hf, seg, ssum, scnt, out);
}

// round 3
// speedup vs baseline: 2.1121x; 2.1121x over previous
#include <cuda_runtime.h>
#include <cuda_bf16.h>
#include <math.h>

// Problem constants
#define BSZ 4
#define SEQ 2048
#define DIM 512
#define NHEAD 8
#define NLAYER 4
#define FFDIM 2048
#define HDIM 64
#define HALFHD 32
#define EPSV 1e-6f
#define ALPHAV 0.5f
#define LOG_ROPE_BASE 9.210340371976184   // ln(10000)

#define BT (BSZ * SEQ)                    // 8192

typedef unsigned int u32;
typedef unsigned long long u64;

// ---------------- scratch layout (single static device buffer) ----------------
constexpr size_t NX    = (size_t)BT * DIM;
constexpr size_t NHID  = (size_t)BT * FFDIM;
constexpr size_t NS    = (size_t)BSZ * NHEAD * SEQ * SEQ;
constexpr size_t NSEGS = (size_t)BSZ * (SEQ + 1) * DIM;
constexpr size_t NSEGC = (size_t)BSZ * (SEQ + 1);
constexpr size_t NROPE = (size_t)SEQ * HALFHD;

constexpr size_t OFF_X    = 0;
constexpr size_t OFF_Y    = OFF_X  + NX;
constexpr size_t OFF_XN   = OFF_Y  + NX;
constexpr size_t OFF_Q    = OFF_XN + NX;
constexpr size_t OFF_K    = OFF_Q  + NX;
constexpr size_t OFF_V    = OFF_K  + NX;
constexpr size_t OFF_QP   = OFF_V  + NX;
constexpr size_t OFF_KP   = OFF_QP + NX;
constexpr size_t OFF_VT   = OFF_KP + NX;   // transposed V [bh, d, t]
constexpr size_t OFF_OP   = OFF_VT + NX;
constexpr size_t OFF_OC   = OFF_OP + NX;
constexpr size_t OFF_HF   = OFF_OC + NX;
constexpr size_t OFF_H1   = OFF_HF + NX;
constexpr size_t OFF_H3   = OFF_H1 + NHID;
constexpr size_t OFF_G    = OFF_H3 + NHID;
constexpr size_t OFF_S    = OFF_G  + NHID;
constexpr size_t OFF_SSUM = OFF_S  + NS;
constexpr size_t OFF_SCNT = OFF_SSUM + NSEGS;
constexpr size_t OFF_COS  = OFF_SCNT + NSEGC;
constexpr size_t OFF_SIN  = OFF_COS + NROPE;
constexpr size_t TOTALF   = OFF_SIN + NROPE;

__device__ float g_buf[TOTALF];
__device__ int   g_seg[BT];

// ---------------- PTX helpers (warp MMA path, sm_100-safe) ----------------
__device__ __forceinline__ u32 smem_u32(const void* p) {
    u32 a;
    asm("{ .reg .u64 t; cvta.to.shared.u64 t, %1; cvt.u32.u64 %0, t; }" : "=r"(a) : "l"(p));
    return a;
}

__device__ __forceinline__ void ldsm4(u32 addr, u32& r0, u32& r1, u32& r2, u32& r3) {
    asm volatile("ldmatrix.sync.aligned.m8n8.x4.shared.b16 {%0,%1,%2,%3}, [%4];"
                 : "=r"(r0), "=r"(r1), "=r"(r2), "=r"(r3) : "r"(addr));
}
__device__ __forceinline__ void ldsm2(u32 addr, u32& r0, u32& r1) {
    asm volatile("ldmatrix.sync.aligned.m8n8.x2.shared.b16 {%0,%1}, [%2];"
                 : "=r"(r0), "=r"(r1) : "r"(addr));
}
__device__ __forceinline__ void mma16816(float* d, u32 a0, u32 a1, u32 a2, u32 a3,
                                         u32 b0, u32 b1) {
    asm volatile(
        "mma.sync.aligned.m16n8k16.row.col.f32.bf16.bf16.f32 "
        "{%0,%1,%2,%3}, {%4,%5,%6,%7}, {%8,%9}, {%0,%1,%2,%3};"
        : "+f"(d[0]), "+f"(d[1]), "+f"(d[2]), "+f"(d[3])
        : "r"(a0), "r"(a1), "r"(a2), "r"(a3), "r"(b0), "r"(b1));
}

// ---------------- misc helpers ----------------
__device__ __forceinline__ bool is_sep(int c) {
    switch (c) {
        case 9: case 10: case 13: case 32: case 33: case 34: case 35: case 36:
        case 37: case 38: case 39: case 40: case 41: case 42: case 43: case 44:
        case 45: case 46: case 47: case 58: case 59: case 60: case 61: case 62:
        case 63: case 64: case 91: case 92: case 93: case 94: case 123:
        case 124: case 125: case 126:
            return true;
        default:
            return false;
    }
}

// ---------------- small kernels ----------------
__global__ void embed_kernel(const int* __restrict__ tokens,
                             const float* __restrict__ embed,
                             float* __restrict__ x) {
    int m = blockIdx.x;
    int tok = tokens[m];
    tok = min(max(tok, 0), 255);
    reinterpret_cast<float4*>(x + (size_t)m * DIM)[threadIdx.x] =
        reinterpret_cast<const float4*>(embed + (size_t)tok * DIM)[threadIdx.x];
}

__global__ void rmsnorm_kernel(const float* __restrict__ x,
                               const float* __restrict__ w,
                               float* __restrict__ o) {
    int row = blockIdx.x;
    const float4 v = reinterpret_cast<const float4*>(x + (size_t)row * DIM)[threadIdx.x];
    float ss = v.x * v.x + v.y * v.y + v.z * v.z + v.w * v.w;
    for (int s = 16; s; s >>= 1) ss += __shfl_xor_sync(0xffffffffu, ss, s);
    __shared__ float red[4];
    int lane = threadIdx.x & 31, wp = threadIdx.x >> 5;
    if (!lane) red[wp] = ss;
    __syncthreads();
    ss = red[0] + red[1] + red[2] + red[3];
    float rs = rsqrtf(ss * (1.0f / DIM) + EPSV);
    float4 wv = reinterpret_cast<const float4*>(w)[threadIdx.x];
    float4 r = make_float4(v.x * rs * wv.x, v.y * rs * wv.y,
                           v.z * rs * wv.z, v.w * rs * wv.w);
    reinterpret_cast<float4*>(o + (size_t)row * DIM)[threadIdx.x] = r;
}

__global__ void rope_table_kernel(float* __restrict__ cosT, float* __restrict__ sinT) {
    int idx = blockIdx.x * blockDim.x + threadIdx.x;
    if (idx >= SEQ * HALFHD) return;
    int t = idx / HALFHD, i = idx % HALFHD;
    double inv = exp(-(double)i * (LOG_ROPE_BASE / (double)HALFHD));
    double ang = (double)t * inv;
    double s, c;
    sincos(ang, &s, &c);
    cosT[idx] = (float)c;
    sinT[idx] = (float)s;
}

// pack q,k:  [B,T,H*DH] -> [B,H,T,DH]; rope both, 1/sqrt(DH) on q
__global__ void pack_rope_kernel(const float* __restrict__ qr,
                                 const float* __restrict__ kr,
                                 const float* __restrict__ cosT,
                                 const float* __restrict__ sinT,
                                 float* __restrict__ qp,
                                 float* __restrict__ kp) {
    int gid = blockIdx.x * blockDim.x + threadIdx.x;
    if (gid >= BSZ * NHEAD * SEQ * HALFHD) return;
    int i = gid % HALFHD;
    int t = (gid / HALFHD) % SEQ;
    int h = (gid / (HALFHD * SEQ)) % NHEAD;
    int b = gid / (HALFHD * SEQ * NHEAD);
    size_t src = ((size_t)b * SEQ + t) * DIM + h * HDIM + 2 * i;
    size_t dst = (((size_t)(b * NHEAD + h)) * SEQ + t) * HDIM + 2 * i;
    float c = cosT[t * HALFHD + i];
    float s = sinT[t * HALFHD + i];
    float2 q2 = *reinterpret_cast<const float2*>(qr + src);
    float2 k2 = *reinterpret_cast<const float2*>(kr + src);
    const float qs = 0.125f; // 1/sqrt(64)
    *reinterpret_cast<float2*>(qp + dst) =
        make_float2((q2.x * c - q2.y * s) * qs, (q2.x * s + q2.y * c) * qs);
    *reinterpret_cast<float2*>(kp + dst) =
        make_float2(k2.x * c - k2.y * s, k2.x * s + k2.y * c);
}

// V transpose: vr [B,T,H*DH] -> vt [B*H, DH, T]
__global__ void vtrans_kernel(const float* __restrict__ vr, float* __restrict__ vt) {
    __shared__ float s[32][33];
    int bh = blockIdx.z;
    int b = bh >> 3, h = bh & 7;
    int t0 = blockIdx.x * 32, d0 = blockIdx.y * 32;
    int tx = threadIdx.x, ty = threadIdx.y;
#pragma unroll
    for (int r = 0; r < 32; r += 8)
        s[ty + r][tx] = vr[((size_t)(b * SEQ) + t0 + ty + r) * DIM + h * HDIM + d0 + tx];
    __syncthreads();
#pragma unroll
    for (int r = 0; r < 32; r += 8)
        vt[((size_t)bh * HDIM + d0 + ty + r) * SEQ + t0 + tx] = s[tx][ty + r];
}

__global__ void softmax_kernel(float* __restrict__ S) {
    constexpr int NTH = 256, PT = SEQ / NTH;
    float* row = S + (size_t)blockIdx.x * SEQ;
    float v[PT];
    float mx = -1e30f;
#pragma unroll
    for (int j = 0; j < PT; j++) {
        v[j] = row[threadIdx.x + j * NTH];
        mx = fmaxf(mx, v[j]);
    }
    __shared__ float red[8];
    int lane = threadIdx.x & 31, wp = threadIdx.x >> 5;
    for (int s = 16; s; s >>= 1) mx = fmaxf(mx, __shfl_xor_sync(0xffffffffu, mx, s));
    if (!lane) red[wp] = mx;
    __syncthreads();
    mx = red[0];
#pragma unroll
    for (int i = 1; i < 8; i++) mx = fmaxf(mx, red[i]);
    float sum = 0.f;
#pragma unroll
    for (int j = 0; j < PT; j++) {
        v[j] = __expf(v[j] - mx);
        sum += v[j];
    }
    for (int s = 16; s; s >>= 1) sum += __shfl_xor_sync(0xffffffffu, sum, s);
    __syncthreads();
    if (!lane) red[wp] = sum;
    __syncthreads();
    sum = red[0];
#pragma unroll
    for (int i = 1; i < 8; i++) sum += red[i];
    float inv = 1.0f / sum;
#pragma unroll
    for (int j = 0; j < PT; j++) row[threadIdx.x + j * NTH] = v[j] * inv;
}

// [B,H,T,DH] -> [B,T,H*DH]
__global__ void unpack_o_kernel(const float* __restrict__ op, float* __restrict__ oc) {
    int m = blockIdx.x;
    int b = m / SEQ, t = m % SEQ;
    int c = threadIdx.x * 4;
    int h = c / HDIM, d = c % HDIM;
    float4 v = *reinterpret_cast<const float4*>(
        op + (((size_t)(b * NHEAD + h)) * SEQ + t) * HDIM + d);
    *reinterpret_cast<float4*>(oc + (size_t)m * DIM + c) = v;
}

__global__ void swiglu_kernel(const float* __restrict__ h1,
                              const float* __restrict__ h3,
                              float* __restrict__ g, size_t n) {
    size_t i = (size_t)blockIdx.x * blockDim.x + threadIdx.x;
    if (i < n) {
        float a = h1[i];
        float s = a / (1.0f + __expf(-a));
        g[i] = s * h3[i];
    }
}

__global__ void zero_kernel(float* __restrict__ p, size_t n) {
    size_t i = (size_t)blockIdx.x * blockDim.x + threadIdx.x;
    size_t stride = (size_t)gridDim.x * blockDim.x;
    for (; i < n; i += stride) p[i] = 0.0f;
}

__global__ void segscan_kernel(const int* __restrict__ tokens, int* __restrict__ seg) {
    int b = blockIdx.x;
    constexpr int PT = SEQ / 256;
    int flags[PT];
    int s = 0;
#pragma unroll
    for (int j = 0; j < PT; j++) {
        int tok = tokens[b * SEQ + threadIdx.x * PT + j];
        tok = min(max(tok, 0), 255);
        flags[j] = is_sep(tok) ? 1 : 0;
        s += flags[j];
    }
    __shared__ int wsum[8];
    int lane = threadIdx.x & 31, wp = threadIdx.x >> 5;
    int ps = s;
    for (int o = 1; o < 32; o <<= 1) {
        int v = __shfl_up_sync(0xffffffffu, ps, o);
        if (lane >= o) ps += v;
    }
    if (lane == 31) wsum[wp] = ps;
    __syncthreads();
    int woff = 0;
    for (int i = 0; i < wp; i++) woff += wsum[i];
    int run = ps - s + woff; // exclusive prefix
#pragma unroll
    for (int j = 0; j < PT; j++) {
        run += flags[j];
        seg[b * SEQ + threadIdx.x * PT + j] = run + b * (SEQ + 1);
    }
}

__global__ void segsum_kernel(const float* __restrict__ h, const int* __restrict__ seg,
                              float* __restrict__ ssum, float* __restrict__ scnt) {
    int m = blockIdx.x;
    int s = seg[m];
    float4 v = reinterpret_cast<const float4*>(h + (size_t)m * DIM)[threadIdx.x];
    float* base = ssum + (size_t)s * DIM + threadIdx.x * 4;
    atomicAdd(base + 0, v.x);
    atomicAdd(base + 1, v.y);
    atomicAdd(base + 2, v.z);
    atomicAdd(base + 3, v.w);
    if (threadIdx.x == 0) atomicAdd(scnt + s, 1.0f);
}

__global__ void pool_kernel(const float* __restrict__ h, const int* __restrict__ seg,
                            const float* __restrict__ ssum, const float* __restrict__ scnt,
                            float* __restrict__ out) {
    int m = blockIdx.x;
    int s = seg[m];
    float inv = 1.0f / fmaxf(scnt[s], 1.0f);
    float4 v = reinterpret_cast<const float4*>(h + (size_t)m * DIM)[threadIdx.x];
    float4 sm = reinterpret_cast<const float4*>(ssum + (size_t)s * DIM)[threadIdx.x];
    float4 r = make_float4(ALPHAV * v.x + (1.0f - ALPHAV) * sm.x * inv,
                           ALPHAV * v.y + (1.0f - ALPHAV) * sm.y * inv,
                           ALPHAV * v.z + (1.0f - ALPHAV) * sm.z * inv,
                           ALPHAV * v.w + (1.0f - ALPHAV) * sm.w * inv);
    reinterpret_cast<float4*>(out + (size_t)m * DIM)[threadIdx.x] = r;
}

// ---------------- warp-MMA GEMM (bf16 split, fp32 acc) ----------------
// C[M,N] = A[M,K] @ B[N,K]^T (+R).  A,B fp32 K-major, C fp32 row-major.
// In-kernel 2-way bf16 split: 3 MMA passes (hh, hl, lh). Batched via blockIdx.z.
// BM=128, BK=32, BN in {64,128}. 256 threads = 8 warps (2 x 4).

constexpr int GBM = 128;
constexpr int GBK = 32;
constexpr int LDB = 80;                     // bytes per bf16 smem row (32*2 + 16 pad)
constexpr int ATILE = GBM * LDB;            // 10240 B per A hi/lo plane

template <int BN>
struct GemmCfg {
    static constexpr int WTN   = BN / 4;            // warp n-tile
    static constexpr int NT    = WTN / 8;           // n8 tiles per warp
    static constexpr int PB    = BN / 32;           // B float4 loads per thread
    static constexpr int BTILE = BN * LDB;
    static constexpr int SBUF  = 2 * ATILE + 2 * BTILE;
    static constexpr int SMEM  = 2 * SBUF;
};

__device__ __forceinline__ void split_pack(float4 v, uint2& hp, uint2& lp) {
    __nv_bfloat162 h01, h23, l01, l23;
    h01.x = __float2bfloat16_rn(v.x);
    h01.y = __float2bfloat16_rn(v.y);
    h23.x = __float2bfloat16_rn(v.z);
    h23.y = __float2bfloat16_rn(v.w);
    l01.x = __float2bfloat16_rn(v.x - __bfloat162float(h01.x));
    l01.y = __float2bfloat16_rn(v.y - __bfloat162float(h01.y));
    l23.x = __float2bfloat16_rn(v.z - __bfloat162float(h23.x));
    l23.y = __float2bfloat16_rn(v.w - __bfloat162float(h23.y));
    hp.x = *reinterpret_cast<u32*>(&h01);
    hp.y = *reinterpret_cast<u32*>(&h23);
    lp.x = *reinterpret_cast<u32*>(&l01);
    lp.y = *reinterpret_cast<u32*>(&l23);
}

template <int BN>
__global__ void __launch_bounds__(256, 1)
gemm_mma_kernel(const float* __restrict__ A, const float* __restrict__ B,
                float* __restrict__ C, const float* __restrict__ R,
                int N, int K, size_t sA, size_t sB, size_t sC) {
    using Cfg = GemmCfg<BN>;
    constexpr int NT = Cfg::NT;
    constexpr int PB = Cfg::PB;

    extern __shared__ __align__(16) char smem[];
    const int tid = threadIdx.x;
    const int lane = tid & 31, wid = tid >> 5;
    const int wy = wid >> 2, wx = wid & 3;   // 2 x 4 warp grid
    const u32 sbase = smem_u32(smem);

    const float* Ab = A + (size_t)blockIdx.z * sA + (size_t)(blockIdx.y * GBM) * K;
    const float* Bb = B + (size_t)blockIdx.z * sB + (size_t)(blockIdx.x * BN) * K;

    float acc[4][NT][4];
#pragma unroll
    for (int i = 0; i < 4; i++)
#pragma unroll
        for (int j = 0; j < NT; j++)
#pragma unroll
            for (int q = 0; q < 4; q++) acc[i][j][q] = 0.f;

    float4 pa[4], pb[PB];
    const int nchunk = K >> 5;

    // ---- load chunk 0 ----
#pragma unroll
    for (int i = 0; i < 4; i++) {
        int f = tid + i * 256;
        pa[i] = *reinterpret_cast<const float4*>(Ab + (size_t)(f >> 3) * K + (f & 7) * 4);
    }
#pragma unroll
    for (int i = 0; i < PB; i++) {
        int f = tid + i * 256;
        pb[i] = *reinterpret_cast<const float4*>(Bb + (size_t)(f >> 3) * K + (f & 7) * 4);
    }
    // store chunk 0 into buffer 0
    {
        char* sAh = smem;
        char* sAl = smem + ATILE;
        char* sBh = smem + 2 * ATILE;
        char* sBl = smem + 2 * ATILE + Cfg::BTILE;
#pragma unroll
        for (int i = 0; i < 4; i++) {
            int f = tid + i * 256;
            int off = (f >> 3) * LDB + (f & 7) * 8;
            uint2 hp, lp;
            split_pack(pa[i], hp, lp);
            *reinterpret_cast<uint2*>(sAh + off) = hp;
            *reinterpret_cast<uint2*>(sAl + off) = lp;
        }
#pragma unroll
        for (int i = 0; i < PB; i++) {
            int f = tid + i * 256;
            int off = (f >> 3) * LDB + (f & 7) * 8;
            uint2 hp, lp;
            split_pack(pb[i], hp, lp);
            *reinterpret_cast<uint2*>(sBh + off) = hp;
            *reinterpret_cast<uint2*>(sBl + off) = lp;
        }
    }
    __syncthreads();

    for (int c = 0; c < nchunk; ++c) {
        // prefetch next chunk into registers
        if (c + 1 < nchunk) {
            const float* An = Ab + (c + 1) * GBK;
            const float* Bn = Bb + (c + 1) * GBK;
#pragma unroll
            for (int i = 0; i < 4; i++) {
                int f = tid + i * 256;
                pa[i] = *reinterpret_cast<const float4*>(An + (size_t)(f >> 3) * K + (f & 7) * 4);
            }
#pragma unroll
            for (int i = 0; i < PB; i++) {
                int f = tid + i * 256;
                pb[i] = *reinterpret_cast<const float4*>(Bn + (size_t)(f >> 3) * K + (f & 7) * 4);
            }
        }

        // compute on buffer c&1
        {
            u32 base = sbase + (u32)((c & 1) * Cfg::SBUF);
            u32 aH = base;
            u32 aL = base + ATILE;
            u32 bH = base + 2 * ATILE;
            u32 bL = base + 2 * ATILE + Cfg::BTILE;

            int arow = wy * 64 + (lane & 15);
            int acol = ((lane >> 4) & 1) * 16;
            int brow = wx * Cfg::WTN + (lane & 7);
            int bcol = ((lane >> 3) & 1) * 16;

#pragma unroll
            for (int ks = 0; ks < 2; ++ks) {
                u32 ah[4][4], al[4][4];
#pragma unroll
                for (int mt = 0; mt < 4; ++mt) {
                    u32 off = (u32)((arow + mt * 16) * LDB + ks * 32 + acol);
                    ldsm4(aH + off, ah[mt][0], ah[mt][1], ah[mt][2], ah[mt][3]);
                    ldsm4(aL + off, al[mt][0], al[mt][1], al[mt][2], al[mt][3]);
                }
                u32 bh[NT][2], bl[NT][2];
#pragma unroll
                for (int nt = 0; nt < NT; ++nt) {
                    u32 off = (u32)((brow + nt * 8) * LDB + ks * 32 + bcol);
                    ldsm2(bH + off, bh[nt][0], bh[nt][1]);
                    ldsm2(bL + off, bl[nt][0], bl[nt][1]);
                }
#pragma unroll
                for (int mt = 0; mt < 4; ++mt)
#pragma unroll
                    for (int nt = 0; nt < NT; ++nt) {
                        mma16816(acc[mt][nt], ah[mt][0], ah[mt][1], ah[mt][2], ah[mt][3],
                                 bh[nt][0], bh[nt][1]);
                        mma16816(acc[mt][nt], ah[mt][0], ah[mt][1], ah[mt][2], ah[mt][3],
                                 bl[nt][0], bl[nt][1]);
                        mma16816(acc[mt][nt], al[mt][0], al[mt][1], al[mt][2], al[mt][3],
                                 bh[nt][0], bh[nt][1]);
                    }
            }
        }

        // store prefetched chunk into the other buffer
        if (c + 1 < nchunk) {
            char* st = smem + ((c + 1) & 1) * Cfg::SBUF;
            char* sAh = st;
            char* sAl = st + ATILE;
            char* sBh = st + 2 * ATILE;
            char* sBl = st + 2 * ATILE + Cfg::BTILE;
#pragma unroll
            for (int i = 0; i < 4; i++) {
                int f = tid + i * 256;
                int off = (f >> 3) * LDB + (f & 7) * 8;
                uint2 hp, lp;
                split_pack(pa[i], hp, lp);
                *reinterpret_cast<uint2*>(sAh + off) = hp;
                *reinterpret_cast<uint2*>(sAl + off) = lp;
            }
#pragma unroll
            for (int i = 0; i < PB; i++) {
                int f = tid + i * 256;
                int off = (f >> 3) * LDB + (f & 7) * 8;
                uint2 hp, lp;
                split_pack(pb[i], hp, lp);
                *reinterpret_cast<uint2*>(sBh + off) = hp;
                *reinterpret_cast<uint2*>(sBl + off) = lp;
            }
            __syncthreads();
        }
    }

    // ---- epilogue ----
    float* Cz = C + (size_t)blockIdx.z * sC;
    const float* Rz = R ? R + (size_t)blockIdx.z * sC : nullptr;
#pragma unroll
    for (int mt = 0; mt < 4; ++mt) {
        int row0 = blockIdx.y * GBM + wy * 64 + mt * 16 + (lane >> 2);
#pragma unroll
        for (int nt = 0; nt < NT; ++nt) {
            int col = blockIdx.x * BN + wx * Cfg::WTN + nt * 8 + (lane & 3) * 2;
            size_t o0 = (size_t)row0 * N + col;
            size_t o1 = (size_t)(row0 + 8) * N + col;
            float2 v0 = make_float2(acc[mt][nt][0], acc[mt][nt][1]);
            float2 v1 = make_float2(acc[mt][nt][2], acc[mt][nt][3]);
            if (Rz) {
                float2 r0 = *reinterpret_cast<const float2*>(Rz + o0);
                float2 r1 = *reinterpret_cast<const float2*>(Rz + o1);
                v0.x += r0.x; v0.y += r0.y;
                v1.x += r1.x; v1.y += r1.y;
            }
            *reinterpret_cast<float2*>(Cz + o0) = v0;
            *reinterpret_cast<float2*>(Cz + o1) = v1;
        }
    }
}

// ---------------- host ----------------
extern "C" void kernel_launch(void* const* d_in, const int* in_sizes, int n_in,
                              void* d_out, int out_size) {
    const int*   tokens       = (const int*)d_in[0];
    const float* embed        = (const float*)d_in[1];
    const float* attn_norm_w  = (const float*)d_in[2];
    const float* wq           = (const float*)d_in[3];
    const float* wk           = (const float*)d_in[4];
    const float* wv           = (const float*)d_in[5];
    const float* wo           = (const float*)d_in[6];
    const float* ffn_norm_w   = (const float*)d_in[7];
    const float* w1           = (const float*)d_in[8];
    const float* w2           = (const float*)d_in[9];
    const float* w3           = (const float*)d_in[10];
    const float* final_norm_w = (const float*)d_in[11];
    float* out = (float*)d_out;

    constexpr int SMEM128 = GemmCfg<128>::SMEM;  // 81920
    constexpr int SMEM64  = GemmCfg<64>::SMEM;   // 61440
    cudaFuncSetAttribute(gemm_mma_kernel<128>,
                         cudaFuncAttributeMaxDynamicSharedMemorySize, SMEM128);
    cudaFuncSetAttribute(gemm_mma_kernel<64>,
                         cudaFuncAttributeMaxDynamicSharedMemorySize, SMEM64);

    float* buf = nullptr;
    cudaGetSymbolAddress((void**)&buf, g_buf);
    int* seg = nullptr;
    cudaGetSymbolAddress((void**)&seg, g_seg);

    float* x    = buf + OFF_X;
    float* y    = buf + OFF_Y;
    float* xn   = buf + OFF_XN;
    float* qr   = buf + OFF_Q;
    float* kr   = buf + OFF_K;
    float* vr   = buf + OFF_V;
    float* qp   = buf + OFF_QP;
    float* kp   = buf + OFF_KP;
    float* vt   = buf + OFF_VT;
    float* op   = buf + OFF_OP;
    float* oc   = buf + OFF_OC;
    float* hf   = buf + OFF_HF;
    float* h1   = buf + OFF_H1;
    float* h3   = buf + OFF_H3;
    float* gg   = buf + OFF_G;
    float* S    = buf + OFF_S;
    float* ssum = buf + OFF_SSUM;
    float* scnt = buf + OFF_SCNT;
    float* cosT = buf + OFF_COS;
    float* sinT = buf + OFF_SIN;

    embed_kernel<<<BT, 128>>>(tokens, embed, x);
    rope_table_kernel<<<(SEQ * HALFHD + 255) / 256, 256>>>(cosT, sinT);

    const size_t strQK = (size_t)SEQ * HDIM;   // per (b,h) q/k/vt stride
    const size_t strS  = (size_t)SEQ * SEQ;    // per (b,h) scores stride

    for (int l = 0; l < NLAYER; l++) {
        const float* wq_l = wq + (size_t)l * DIM * DIM;
        const float* wk_l = wk + (size_t)l * DIM * DIM;
        const float* wv_l = wv + (size_t)l * DIM * DIM;
        const float* wo_l = wo + (size_t)l * DIM * DIM;
        const float* w1_l = w1 + (size_t)l * FFDIM * DIM;
        const float* w2_l = w2 + (size_t)l * DIM * FFDIM;
        const float* w3_l = w3 + (size_t)l * FFDIM * DIM;

        rmsnorm_kernel<<<BT, 128>>>(x, attn_norm_w + (size_t)l * DIM, xn);

        // QKV projections: [8192,512] = [8192,512] @ [512,512]^T
        dim3 gproj(DIM / 128, BT / 128, 1);
        gemm_mma_kernel<128><<<gproj, 256, SMEM128>>>(xn, wq_l, qr, nullptr, DIM, DIM, 0, 0, 0);
        gemm_mma_kernel<128><<<gproj, 256, SMEM128>>>(xn, wk_l, kr, nullptr, DIM, DIM, 0, 0, 0);
        gemm_mma_kernel<128><<<gproj, 256, SMEM128>>>(xn, wv_l, vr, nullptr, DIM, DIM, 0, 0, 0);

        pack_rope_kernel<<<(BSZ * NHEAD * SEQ * HALFHD + 255) / 256, 256>>>(
            qr, kr, cosT, sinT, qp, kp);
        vtrans_kernel<<<dim3(SEQ / 32, HDIM / 32, BSZ * NHEAD), dim3(32, 8)>>>(vr, vt);

        // scores: per (b,h) [2048,2048] = Q @ K^T
        dim3 gs(SEQ / 128, SEQ / 128, BSZ * NHEAD);
        gemm_mma_kernel<128><<<gs, 256, SMEM128>>>(qp, kp, S, nullptr,
                                                   SEQ, HDIM, strQK, strQK, strS);

        softmax_kernel<<<BSZ * NHEAD * SEQ, 256>>>(S);

        // O = P @ V : per (b,h) [2048,64] = P[2048,2048] @ vt[64,2048]^T
        dim3 gpv(1, SEQ / 128, BSZ * NHEAD);
        gemm_mma_kernel<64><<<gpv, 256, SMEM64>>>(S, vt, op, nullptr,
                                                  HDIM, SEQ, strS, strQK, strQK);

        unpack_o_kernel<<<BT, 128>>>(op, oc);

        // y = x + O @ Wo^T
        gemm_mma_kernel<128><<<gproj, 256, SMEM128>>>(oc, wo_l, y, x, DIM, DIM, 0, 0, 0);

        rmsnorm_kernel<<<BT, 128>>>(y, ffn_norm_w + (size_t)l * DIM, xn);

        dim3 gff(FFDIM / 128, BT / 128, 1);
        gemm_mma_kernel<128><<<gff, 256, SMEM128>>>(xn, w1_l, h1, nullptr, FFDIM, DIM, 0, 0, 0);
        gemm_mma_kernel<128><<<gff, 256, SMEM128>>>(xn, w3_l, h3, nullptr, FFDIM, DIM, 0, 0, 0);

        swiglu_kernel<<<(int)((NHID + 255) / 256), 256>>>(h1, h3, gg, NHID);

        // x = y + g @ W2^T   (K = 2048)
        gemm_mma_kernel<128><<<gproj, 256, SMEM128>>>(gg, w2_l, x, y, DIM, FFDIM, 0, 0, 0);
    }

    rmsnorm_kernel<<<BT, 128>>>(x, final_norm_w, hf);

    segscan_kernel<<<BSZ, 256>>>(tokens, seg);
    zero_kernel<<<4096, 256>>>(ssum, NSEGS + NSEGC);
    segsum_kernel<<<BT, 128>>>(hf, seg, ssum, scnt);
    pool_kernel<<<BT, 128>>>(hf, seg, ssum, scnt, out);
}

// round 4
// speedup vs baseline: 2.7092x; 1.2827x over previous
#include <cuda_runtime.h>
#include <cuda_bf16.h>
#include <math.h>

// Problem constants
#define BSZ 4
#define SEQ 2048
#define DIM 512
#define NHEAD 8
#define NLAYER 4
#define FFDIM 2048
#define HDIM 64
#define HALFHD 32
#define EPSV 1e-6f
#define ALPHAV 0.5f
#define LOG_ROPE_BASE 9.210340371976184   // ln(10000)

#define BT (BSZ * SEQ)                    // 8192

typedef unsigned int u32;
typedef unsigned long long u64;

// ---------------- scratch layout (single static device buffer) ----------------
constexpr size_t NX    = (size_t)BT * DIM;
constexpr size_t NHID  = (size_t)BT * FFDIM;
constexpr size_t NSEGS = (size_t)BSZ * (SEQ + 1) * DIM;
constexpr size_t NSEGC = (size_t)BSZ * (SEQ + 1);
constexpr size_t NROPE = (size_t)SEQ * HALFHD;

constexpr size_t OFF_X    = 0;
constexpr size_t OFF_Y    = OFF_X  + NX;
constexpr size_t OFF_XN   = OFF_Y  + NX;
constexpr size_t OFF_Q    = OFF_XN + NX;
constexpr size_t OFF_K    = OFF_Q  + NX;
constexpr size_t OFF_V    = OFF_K  + NX;
constexpr size_t OFF_QP   = OFF_V  + NX;
constexpr size_t OFF_KP   = OFF_QP + NX;
constexpr size_t OFF_VT   = OFF_KP + NX;   // transposed V [bh, d, t]
constexpr size_t OFF_OC   = OFF_VT + NX;
constexpr size_t OFF_HF   = OFF_OC + NX;
constexpr size_t OFF_H1   = OFF_HF + NX;
constexpr size_t OFF_H3   = OFF_H1 + NHID;
constexpr size_t OFF_G    = OFF_H3 + NHID;
constexpr size_t OFF_SSUM = OFF_G  + NHID;
constexpr size_t OFF_SCNT = OFF_SSUM + NSEGS;
constexpr size_t OFF_COS  = OFF_SCNT + NSEGC;
constexpr size_t OFF_SIN  = OFF_COS + NROPE;
constexpr size_t TOTALF   = OFF_SIN + NROPE;

__device__ float g_buf[TOTALF];
__device__ int   g_seg[BT];

// ---------------- PTX helpers (warp MMA path, sm_100-safe) ----------------
__device__ __forceinline__ u32 smem_u32(const void* p) {
    u32 a;
    asm("{ .reg .u64 t; cvta.to.shared.u64 t, %1; cvt.u32.u64 %0, t; }" : "=r"(a) : "l"(p));
    return a;
}

__device__ __forceinline__ void ldsm4(u32 addr, u32& r0, u32& r1, u32& r2, u32& r3) {
    asm volatile("ldmatrix.sync.aligned.m8n8.x4.shared.b16 {%0,%1,%2,%3}, [%4];"
                 : "=r"(r0), "=r"(r1), "=r"(r2), "=r"(r3) : "r"(addr));
}
__device__ __forceinline__ void ldsm2(u32 addr, u32& r0, u32& r1) {
    asm volatile("ldmatrix.sync.aligned.m8n8.x2.shared.b16 {%0,%1}, [%2];"
                 : "=r"(r0), "=r"(r1) : "r"(addr));
}
__device__ __forceinline__ void mma16816(float* d, u32 a0, u32 a1, u32 a2, u32 a3,
                                         u32 b0, u32 b1) {
    asm volatile(
        "mma.sync.aligned.m16n8k16.row.col.f32.bf16.bf16.f32 "
        "{%0,%1,%2,%3}, {%4,%5,%6,%7}, {%8,%9}, {%0,%1,%2,%3};"
        : "+f"(d[0]), "+f"(d[1]), "+f"(d[2]), "+f"(d[3])
        : "r"(a0), "r"(a1), "r"(a2), "r"(a3), "r"(b0), "r"(b1));
}
__device__ __forceinline__ void cp16(u32 dst, const void* src) {
    asm volatile("cp.async.cg.shared.global [%0], [%1], 16;" :: "r"(dst), "l"(src));
}
__device__ __forceinline__ void cp_commit() { asm volatile("cp.async.commit_group;"); }
__device__ __forceinline__ void cp_wait0()  { asm volatile("cp.async.wait_group 0;" ::: "memory"); }

__device__ __forceinline__ void split_pack(float4 v, uint2& hp, uint2& lp) {
    __nv_bfloat162 h01, h23, l01, l23;
    h01.x = __float2bfloat16_rn(v.x);
    h01.y = __float2bfloat16_rn(v.y);
    h23.x = __float2bfloat16_rn(v.z);
    h23.y = __float2bfloat16_rn(v.w);
    l01.x = __float2bfloat16_rn(v.x - __bfloat162float(h01.x));
    l01.y = __float2bfloat16_rn(v.y - __bfloat162float(h01.y));
    l23.x = __float2bfloat16_rn(v.z - __bfloat162float(h23.x));
    l23.y = __float2bfloat16_rn(v.w - __bfloat162float(h23.y));
    hp.x = *reinterpret_cast<u32*>(&h01);
    hp.y = *reinterpret_cast<u32*>(&h23);
    lp.x = *reinterpret_cast<u32*>(&l01);
    lp.y = *reinterpret_cast<u32*>(&l23);
}

__device__ __forceinline__ void split2(float x, float y, u32& hi, u32& lo) {
    __nv_bfloat162 h, l;
    h.x = __float2bfloat16_rn(x);
    h.y = __float2bfloat16_rn(y);
    l.x = __float2bfloat16_rn(x - __bfloat162float(h.x));
    l.y = __float2bfloat16_rn(y - __bfloat162float(h.y));
    hi = *reinterpret_cast<u32*>(&h);
    lo = *reinterpret_cast<u32*>(&l);
}

// ---------------- misc helpers ----------------
__device__ __forceinline__ bool is_sep(int c) {
    switch (c) {
        case 9: case 10: case 13: case 32: case 33: case 34: case 35: case 36:
        case 37: case 38: case 39: case 40: case 41: case 42: case 43: case 44:
        case 45: case 46: case 47: case 58: case 59: case 60: case 61: case 62:
        case 63: case 64: case 91: case 92: case 93: case 94: case 123:
        case 124: case 125: case 126:
            return true;
        default:
            return false;
    }
}

// ---------------- small kernels ----------------
__global__ void embed_kernel(const int* __restrict__ tokens,
                             const float* __restrict__ embed,
                             float* __restrict__ x) {
    int m = blockIdx.x;
    int tok = tokens[m];
    tok = min(max(tok, 0), 255);
    reinterpret_cast<float4*>(x + (size_t)m * DIM)[threadIdx.x] =
        reinterpret_cast<const float4*>(embed + (size_t)tok * DIM)[threadIdx.x];
}

__global__ void rmsnorm_kernel(const float* __restrict__ x,
                               const float* __restrict__ w,
                               float* __restrict__ o) {
    int row = blockIdx.x;
    const float4 v = reinterpret_cast<const float4*>(x + (size_t)row * DIM)[threadIdx.x];
    float ss = v.x * v.x + v.y * v.y + v.z * v.z + v.w * v.w;
    for (int s = 16; s; s >>= 1) ss += __shfl_xor_sync(0xffffffffu, ss, s);
    __shared__ float red[4];
    int lane = threadIdx.x & 31, wp = threadIdx.x >> 5;
    if (!lane) red[wp] = ss;
    __syncthreads();
    ss = red[0] + red[1] + red[2] + red[3];
    float rs = rsqrtf(ss * (1.0f / DIM) + EPSV);
    float4 wv = reinterpret_cast<const float4*>(w)[threadIdx.x];
    float4 r = make_float4(v.x * rs * wv.x, v.y * rs * wv.y,
                           v.z * rs * wv.z, v.w * rs * wv.w);
    reinterpret_cast<float4*>(o + (size_t)row * DIM)[threadIdx.x] = r;
}

__global__ void rope_table_kernel(float* __restrict__ cosT, float* __restrict__ sinT) {
    int idx = blockIdx.x * blockDim.x + threadIdx.x;
    if (idx >= SEQ * HALFHD) return;
    int t = idx / HALFHD, i = idx % HALFHD;
    double inv = exp(-(double)i * (LOG_ROPE_BASE / (double)HALFHD));
    double ang = (double)t * inv;
    double s, c;
    sincos(ang, &s, &c);
    cosT[idx] = (float)c;
    sinT[idx] = (float)s;
}

// pack q,k:  [B,T,H*DH] -> [B,H,T,DH]; rope both, 1/sqrt(DH) on q
__global__ void pack_rope_kernel(const float* __restrict__ qr,
                                 const float* __restrict__ kr,
                                 const float* __restrict__ cosT,
                                 const float* __restrict__ sinT,
                                 float* __restrict__ qp,
                                 float* __restrict__ kp) {
    int gid = blockIdx.x * blockDim.x + threadIdx.x;
    if (gid >= BSZ * NHEAD * SEQ * HALFHD) return;
    int i = gid % HALFHD;
    int t = (gid / HALFHD) % SEQ;
    int h = (gid / (HALFHD * SEQ)) % NHEAD;
    int b = gid / (HALFHD * SEQ * NHEAD);
    size_t src = ((size_t)b * SEQ + t) * DIM + h * HDIM + 2 * i;
    size_t dst = (((size_t)(b * NHEAD + h)) * SEQ + t) * HDIM + 2 * i;
    float c = cosT[t * HALFHD + i];
    float s = sinT[t * HALFHD + i];
    float2 q2 = *reinterpret_cast<const float2*>(qr + src);
    float2 k2 = *reinterpret_cast<const float2*>(kr + src);
    const float qs = 0.125f; // 1/sqrt(64)
    *reinterpret_cast<float2*>(qp + dst) =
        make_float2((q2.x * c - q2.y * s) * qs, (q2.x * s + q2.y * c) * qs);
    *reinterpret_cast<float2*>(kp + dst) =
        make_float2(k2.x * c - k2.y * s, k2.x * s + k2.y * c);
}

// V transpose: vr [B,T,H*DH] -> vt [B*H, DH, T]
__global__ void vtrans_kernel(const float* __restrict__ vr, float* __restrict__ vt) {
    __shared__ float s[32][33];
    int bh = blockIdx.z;
    int b = bh >> 3, h = bh & 7;
    int t0 = blockIdx.x * 32, d0 = blockIdx.y * 32;
    int tx = threadIdx.x, ty = threadIdx.y;
#pragma unroll
    for (int r = 0; r < 32; r += 8)
        s[ty + r][tx] = vr[((size_t)(b * SEQ) + t0 + ty + r) * DIM + h * HDIM + d0 + tx];
    __syncthreads();
#pragma unroll
    for (int r = 0; r < 32; r += 8)
        vt[((size_t)bh * HDIM + d0 + ty + r) * SEQ + t0 + tx] = s[tx][ty + r];
}

__global__ void swiglu_kernel(const float* __restrict__ h1,
                              const float* __restrict__ h3,
                              float* __restrict__ g, size_t n) {
    size_t i = (size_t)blockIdx.x * blockDim.x + threadIdx.x;
    if (i < n) {
        float a = h1[i];
        float s = a / (1.0f + __expf(-a));
        g[i] = s * h3[i];
    }
}

__global__ void zero_kernel(float* __restrict__ p, size_t n) {
    size_t i = (size_t)blockIdx.x * blockDim.x + threadIdx.x;
    size_t stride = (size_t)gridDim.x * blockDim.x;
    for (; i < n; i += stride) p[i] = 0.0f;
}

__global__ void segscan_kernel(const int* __restrict__ tokens, int* __restrict__ seg) {
    int b = blockIdx.x;
    constexpr int PT = SEQ / 256;
    int flags[PT];
    int s = 0;
#pragma unroll
    for (int j = 0; j < PT; j++) {
        int tok = tokens[b * SEQ + threadIdx.x * PT + j];
        tok = min(max(tok, 0), 255);
        flags[j] = is_sep(tok) ? 1 : 0;
        s += flags[j];
    }
    __shared__ int wsum[8];
    int lane = threadIdx.x & 31, wp = threadIdx.x >> 5;
    int ps = s;
    for (int o = 1; o < 32; o <<= 1) {
        int v = __shfl_up_sync(0xffffffffu, ps, o);
        if (lane >= o) ps += v;
    }
    if (lane == 31) wsum[wp] = ps;
    __syncthreads();
    int woff = 0;
    for (int i = 0; i < wp; i++) woff += wsum[i];
    int run = ps - s + woff; // exclusive prefix
#pragma unroll
    for (int j = 0; j < PT; j++) {
        run += flags[j];
        seg[b * SEQ + threadIdx.x * PT + j] = run + b * (SEQ + 1);
    }
}

__global__ void segsum_kernel(const float* __restrict__ h, const int* __restrict__ seg,
                              float* __restrict__ ssum, float* __restrict__ scnt) {
    int m = blockIdx.x;
    int s = seg[m];
    float4 v = reinterpret_cast<const float4*>(h + (size_t)m * DIM)[threadIdx.x];
    float* base = ssum + (size_t)s * DIM + threadIdx.x * 4;
    atomicAdd(base + 0, v.x);
    atomicAdd(base + 1, v.y);
    atomicAdd(base + 2, v.z);
    atomicAdd(base + 3, v.w);
    if (threadIdx.x == 0) atomicAdd(scnt + s, 1.0f);
}

__global__ void pool_kernel(const float* __restrict__ h, const int* __restrict__ seg,
                            const float* __restrict__ ssum, const float* __restrict__ scnt,
                            float* __restrict__ out) {
    int m = blockIdx.x;
    int s = seg[m];
    float inv = 1.0f / fmaxf(scnt[s], 1.0f);
    float4 v = reinterpret_cast<const float4*>(h + (size_t)m * DIM)[threadIdx.x];
    float4 sm = reinterpret_cast<const float4*>(ssum + (size_t)s * DIM)[threadIdx.x];
    float4 r = make_float4(ALPHAV * v.x + (1.0f - ALPHAV) * sm.x * inv,
                           ALPHAV * v.y + (1.0f - ALPHAV) * sm.y * inv,
                           ALPHAV * v.z + (1.0f - ALPHAV) * sm.z * inv,
                           ALPHAV * v.w + (1.0f - ALPHAV) * sm.w * inv);
    reinterpret_cast<float4*>(out + (size_t)m * DIM)[threadIdx.x] = r;
}

// ---------------- fused flash attention ----------------
// Per CTA: q-tile of 128 rows for one (b,h). 8 warps x 16 rows.
// Q/K bf16 hi+lo planes (LDQK=144B rows), V^T planes (LDV=272B rows),
// cp.async fp32 staging double-duty buffer, online softmax in registers,
// 3-pass split-mma for both QK and PV. Writes O straight into [B,T,512].

constexpr int FT = 128;                 // kv tile
constexpr int LDQK = 144;               // 64 bf16 + 16B pad
constexpr int LDV  = 272;               // 128 bf16 + 16B pad
constexpr u32 SQH = 0;
constexpr u32 SQL = 18432;
constexpr u32 SKH = 36864;
constexpr u32 SKL = 55296;
constexpr u32 SVH = 73728;
constexpr u32 SVL = 91136;
constexpr u32 SKST = 108544;            // fp32 K staging 32KB
constexpr u32 SVST = 141312;            // fp32 V staging 32KB
constexpr int FLASH_SMEM = 174080;

__global__ void __launch_bounds__(256, 1)
flash_kernel(const float* __restrict__ qp, const float* __restrict__ kp,
             const float* __restrict__ vt, float* __restrict__ oc) {
    extern __shared__ __align__(16) char smem[];
    const u32 sb = smem_u32(smem);
    const int tid = threadIdx.x;
    const int lane = tid & 31, wid = tid >> 5;
    const int qt = blockIdx.x, bh = blockIdx.y;
    const int b = bh >> 3, h = bh & 7;

    const float* Qg = qp + ((size_t)bh * SEQ + qt * 128) * HDIM;
    const float* Kg = kp + (size_t)bh * SEQ * HDIM;
    const float* Vg = vt + (size_t)bh * HDIM * SEQ;

    // Q -> smem split planes (once)
#pragma unroll
    for (int i = 0; i < 8; i++) {
        int idx = tid + i * 256;
        float4 v = *reinterpret_cast<const float4*>(Qg + (size_t)(idx >> 4) * HDIM + (idx & 15) * 4);
        uint2 hp, lp;
        split_pack(v, hp, lp);
        int off = (idx >> 4) * LDQK + (idx & 15) * 8;
        *reinterpret_cast<uint2*>(smem + SQH + off) = hp;
        *reinterpret_cast<uint2*>(smem + SQL + off) = lp;
    }

    // prefetch tile 0 K/V into fp32 staging
#pragma unroll
    for (int i = 0; i < 8; i++) {
        int idx = tid + i * 256;
        cp16(sb + SKST + idx * 16, Kg + (size_t)(idx >> 4) * HDIM + (idx & 15) * 4);
        cp16(sb + SVST + idx * 16, Vg + (size_t)(idx >> 5) * SEQ + (idx & 31) * 4);
    }
    cp_commit();

    float accO[8][4];
#pragma unroll
    for (int i = 0; i < 8; i++)
#pragma unroll
        for (int j = 0; j < 4; j++) accO[i][j] = 0.f;
    float m0 = -1e30f, m1 = -1e30f, l0 = 0.f, l1 = 0.f;

    const int arow = wid * 16 + (lane & 15);
    const int acol = ((lane >> 4) & 1) * 16;
    const int brow = lane & 7;
    const int bcol = ((lane >> 3) & 1) * 16;

    constexpr int NTILE = SEQ / FT; // 16
    for (int t = 0; t < NTILE; t++) {
        cp_wait0();
        __syncthreads();
        // convert staging -> bf16 hi/lo planes
#pragma unroll
        for (int i = 0; i < 8; i++) {
            int idx = tid + i * 256;
            float4 kv = *reinterpret_cast<const float4*>(smem + SKST + idx * 16);
            uint2 hp, lp;
            split_pack(kv, hp, lp);
            int off = (idx >> 4) * LDQK + (idx & 15) * 8;
            *reinterpret_cast<uint2*>(smem + SKH + off) = hp;
            *reinterpret_cast<uint2*>(smem + SKL + off) = lp;
            float4 vv = *reinterpret_cast<const float4*>(smem + SVST + idx * 16);
            split_pack(vv, hp, lp);
            off = (idx >> 5) * LDV + (idx & 31) * 8;
            *reinterpret_cast<uint2*>(smem + SVH + off) = hp;
            *reinterpret_cast<uint2*>(smem + SVL + off) = lp;
        }
        __syncthreads();
        // prefetch next tile (staging reads all done at the sync above)
        if (t + 1 < NTILE) {
            const float* Kn = Kg + (size_t)(t + 1) * FT * HDIM;
            const float* Vn = Vg + (t + 1) * FT;
#pragma unroll
            for (int i = 0; i < 8; i++) {
                int idx = tid + i * 256;
                cp16(sb + SKST + idx * 16, Kn + (size_t)(idx >> 4) * HDIM + (idx & 15) * 4);
                cp16(sb + SVST + idx * 16, Vn + (size_t)(idx >> 5) * SEQ + (idx & 31) * 4);
            }
            cp_commit();
        }

        // ---- S = Q K^T (128x128 per CTA, 16x128 per warp) ----
        float acc[16][4];
#pragma unroll
        for (int i = 0; i < 16; i++)
#pragma unroll
            for (int j = 0; j < 4; j++) acc[i][j] = 0.f;

        u32 qh[4][4], ql[4][4];
#pragma unroll
        for (int ks = 0; ks < 4; ks++) {
            u32 off = (u32)(arow * LDQK + ks * 32 + acol);
            ldsm4(sb + SQH + off, qh[ks][0], qh[ks][1], qh[ks][2], qh[ks][3]);
            ldsm4(sb + SQL + off, ql[ks][0], ql[ks][1], ql[ks][2], ql[ks][3]);
        }
#pragma unroll
        for (int nt = 0; nt < 16; nt++) {
#pragma unroll
            for (int ks = 0; ks < 4; ks++) {
                u32 off = (u32)((nt * 8 + brow) * LDQK + ks * 32 + bcol);
                u32 b0, b1, c0, c1;
                ldsm2(sb + SKH + off, b0, b1);
                ldsm2(sb + SKL + off, c0, c1);
                mma16816(acc[nt], qh[ks][0], qh[ks][1], qh[ks][2], qh[ks][3], b0, b1);
                mma16816(acc[nt], qh[ks][0], qh[ks][1], qh[ks][2], qh[ks][3], c0, c1);
                mma16816(acc[nt], ql[ks][0], ql[ks][1], ql[ks][2], ql[ks][3], b0, b1);
            }
        }

        // ---- online softmax (rows live in 4-lane groups) ----
        float tm0 = -1e30f, tm1 = -1e30f;
#pragma unroll
        for (int nt = 0; nt < 16; nt++) {
            tm0 = fmaxf(tm0, fmaxf(acc[nt][0], acc[nt][1]));
            tm1 = fmaxf(tm1, fmaxf(acc[nt][2], acc[nt][3]));
        }
        tm0 = fmaxf(tm0, __shfl_xor_sync(0xffffffffu, tm0, 1));
        tm0 = fmaxf(tm0, __shfl_xor_sync(0xffffffffu, tm0, 2));
        tm1 = fmaxf(tm1, __shfl_xor_sync(0xffffffffu, tm1, 1));
        tm1 = fmaxf(tm1, __shfl_xor_sync(0xffffffffu, tm1, 2));
        float mn0 = fmaxf(m0, tm0), mn1 = fmaxf(m1, tm1);
        float a0 = __expf(m0 - mn0), a1 = __expf(m1 - mn1);
        m0 = mn0;
        m1 = mn1;
        float s0 = 0.f, s1 = 0.f;
#pragma unroll
        for (int nt = 0; nt < 16; nt++) {
            acc[nt][0] = __expf(acc[nt][0] - m0);
            acc[nt][1] = __expf(acc[nt][1] - m0);
            acc[nt][2] = __expf(acc[nt][2] - m1);
            acc[nt][3] = __expf(acc[nt][3] - m1);
            s0 += acc[nt][0] + acc[nt][1];
            s1 += acc[nt][2] + acc[nt][3];
        }
        s0 += __shfl_xor_sync(0xffffffffu, s0, 1);
        s0 += __shfl_xor_sync(0xffffffffu, s0, 2);
        s1 += __shfl_xor_sync(0xffffffffu, s1, 1);
        s1 += __shfl_xor_sync(0xffffffffu, s1, 2);
        l0 = l0 * a0 + s0;
        l1 = l1 * a1 + s1;
#pragma unroll
        for (int on = 0; on < 8; on++) {
            accO[on][0] *= a0;
            accO[on][1] *= a0;
            accO[on][2] *= a1;
            accO[on][3] *= a1;
        }

        // ---- O += P V  (P from acc, split hi/lo) ----
#pragma unroll
        for (int ks = 0; ks < 8; ks++) {
            u32 ah[4], al[4];
            split2(acc[2 * ks][0], acc[2 * ks][1], ah[0], al[0]);
            split2(acc[2 * ks][2], acc[2 * ks][3], ah[1], al[1]);
            split2(acc[2 * ks + 1][0], acc[2 * ks + 1][1], ah[2], al[2]);
            split2(acc[2 * ks + 1][2], acc[2 * ks + 1][3], ah[3], al[3]);
#pragma unroll
            for (int on = 0; on < 8; on++) {
                u32 off = (u32)((on * 8 + brow) * LDV + ks * 32 + bcol);
                u32 b0, b1, c0, c1;
                ldsm2(sb + SVH + off, b0, b1);
                ldsm2(sb + SVL + off, c0, c1);
                mma16816(accO[on], ah[0], ah[1], ah[2], ah[3], b0, b1);
                mma16816(accO[on], ah[0], ah[1], ah[2], ah[3], c0, c1);
                mma16816(accO[on], al[0], al[1], al[2], al[3], b0, b1);
            }
        }
        __syncthreads();  // done reading K/V planes before next tile overwrites
    }

    // ---- epilogue: O /= l, write directly to [B,T,512] layout ----
    float i0 = 1.0f / l0, i1 = 1.0f / l1;
    int t0 = qt * 128 + wid * 16 + (lane >> 2);
    size_t base0 = ((size_t)b * SEQ + t0) * DIM + h * HDIM;
    size_t base1 = ((size_t)b * SEQ + t0 + 8) * DIM + h * HDIM;
#pragma unroll
    for (int on = 0; on < 8; on++) {
        int d = on * 8 + (lane & 3) * 2;
        *reinterpret_cast<float2*>(oc + base0 + d) =
            make_float2(accO[on][0] * i0, accO[on][1] * i0);
        *reinterpret_cast<float2*>(oc + base1 + d) =
            make_float2(accO[on][2] * i1, accO[on][3] * i1);
    }
}

// ---------------- warp-MMA GEMM (bf16 split, fp32 acc) ----------------
// C[M,N] = A[M,K] @ B[N,K]^T (+R).  A,B fp32 K-major, C fp32 row-major.
// In-kernel 2-way bf16 split: 3 MMA passes (hh, hl, lh). Batched via blockIdx.z.
// BM=128, BK=32, BN in {64,128}. 256 threads = 8 warps (2 x 4).

constexpr int GBM = 128;
constexpr int GBK = 32;
constexpr int LDB = 80;                     // bytes per bf16 smem row (32*2 + 16 pad)
constexpr int ATILE = GBM * LDB;            // 10240 B per A hi/lo plane

template <int BN>
struct GemmCfg {
    static constexpr int WTN   = BN / 4;            // warp n-tile
    static constexpr int NT    = WTN / 8;           // n8 tiles per warp
    static constexpr int PB    = BN / 32;           // B float4 loads per thread
    static constexpr int BTILE = BN * LDB;
    static constexpr int SBUF  = 2 * ATILE + 2 * BTILE;
    static constexpr int SMEM  = 2 * SBUF;
};

template <int BN>
__global__ void __launch_bounds__(256, 1)
gemm_mma_kernel(const float* __restrict__ A, const float* __restrict__ B,
                float* __restrict__ C, const float* __restrict__ R,
                int N, int K, size_t sA, size_t sB, size_t sC) {
    using Cfg = GemmCfg<BN>;
    constexpr int NT = Cfg::NT;
    constexpr int PB = Cfg::PB;

    extern __shared__ __align__(16) char smem[];
    const int tid = threadIdx.x;
    const int lane = tid & 31, wid = tid >> 5;
    const int wy = wid >> 2, wx = wid & 3;   // 2 x 4 warp grid
    const u32 sbase = smem_u32(smem);

    const float* Ab = A + (size_t)blockIdx.z * sA + (size_t)(blockIdx.y * GBM) * K;
    const float* Bb = B + (size_t)blockIdx.z * sB + (size_t)(blockIdx.x * BN) * K;

    float acc[4][NT][4];
#pragma unroll
    for (int i = 0; i < 4; i++)
#pragma unroll
        for (int j = 0; j < NT; j++)
#pragma unroll
            for (int q = 0; q < 4; q++) acc[i][j][q] = 0.f;

    float4 pa[4], pb[PB];
    const int nchunk = K >> 5;

    // ---- load chunk 0 ----
#pragma unroll
    for (int i = 0; i < 4; i++) {
        int f = tid + i * 256;
        pa[i] = *reinterpret_cast<const float4*>(Ab + (size_t)(f >> 3) * K + (f & 7) * 4);
    }
#pragma unroll
    for (int i = 0; i < PB; i++) {
        int f = tid + i * 256;
        pb[i] = *reinterpret_cast<const float4*>(Bb + (size_t)(f >> 3) * K + (f & 7) * 4);
    }
    // store chunk 0 into buffer 0
    {
        char* sAh = smem;
        char* sAl = smem + ATILE;
        char* sBh = smem + 2 * ATILE;
        char* sBl = smem + 2 * ATILE + Cfg::BTILE;
#pragma unroll
        for (int i = 0; i < 4; i++) {
            int f = tid + i * 256;
            int off = (f >> 3) * LDB + (f & 7) * 8;
            uint2 hp, lp;
            split_pack(pa[i], hp, lp);
            *reinterpret_cast<uint2*>(sAh + off) = hp;
            *reinterpret_cast<uint2*>(sAl + off) = lp;
        }
#pragma unroll
        for (int i = 0; i < PB; i++) {
            int f = tid + i * 256;
            int off = (f >> 3) * LDB + (f & 7) * 8;
            uint2 hp, lp;
            split_pack(pb[i], hp, lp);
            *reinterpret_cast<uint2*>(sBh + off) = hp;
            *reinterpret_cast<uint2*>(sBl + off) = lp;
        }
    }
    __syncthreads();

    for (int c = 0; c < nchunk; ++c) {
        // prefetch next chunk into registers
        if (c + 1 < nchunk) {
            const float* An = Ab + (c + 1) * GBK;
            const float* Bn = Bb + (c + 1) * GBK;
#pragma unroll
            for (int i = 0; i < 4; i++) {
                int f = tid + i * 256;
                pa[i] = *reinterpret_cast<const float4*>(An + (size_t)(f >> 3) * K + (f & 7) * 4);
            }
#pragma unroll
            for (int i = 0; i < PB; i++) {
                int f = tid + i * 256;
                pb[i] = *reinterpret_cast<const float4*>(Bn + (size_t)(f >> 3) * K + (f & 7) * 4);
            }
        }

        // compute on buffer c&1
        {
            u32 base = sbase + (u32)((c & 1) * Cfg::SBUF);
            u32 aH = base;
            u32 aL = base + ATILE;
            u32 bH = base + 2 * ATILE;
            u32 bL = base + 2 * ATILE + Cfg::BTILE;

            int arow = wy * 64 + (lane & 15);
            int acol = ((lane >> 4) & 1) * 16;
            int brow = wx * Cfg::WTN + (lane & 7);
            int bcol = ((lane >> 3) & 1) * 16;

#pragma unroll
            for (int ks = 0; ks < 2; ++ks) {
                u32 ah[4][4], al[4][4];
#pragma unroll
                for (int mt = 0; mt < 4; ++mt) {
                    u32 off = (u32)((arow + mt * 16) * LDB + ks * 32 + acol);
                    ldsm4(aH + off, ah[mt][0], ah[mt][1], ah[mt][2], ah[mt][3]);
                    ldsm4(aL + off, al[mt][0], al[mt][1], al[mt][2], al[mt][3]);
                }
                u32 bh[NT][2], bl[NT][2];
#pragma unroll
                for (int nt = 0; nt < NT; ++nt) {
                    u32 off = (u32)((brow + nt * 8) * LDB + ks * 32 + bcol);
                    ldsm2(bH + off, bh[nt][0], bh[nt][1]);
                    ldsm2(bL + off, bl[nt][0], bl[nt][1]);
                }
#pragma unroll
                for (int mt = 0; mt < 4; ++mt)
#pragma unroll
                    for (int nt = 0; nt < NT; ++nt) {
                        mma16816(acc[mt][nt], ah[mt][0], ah[mt][1], ah[mt][2], ah[mt][3],
                                 bh[nt][0], bh[nt][1]);
                        mma16816(acc[mt][nt], ah[mt][0], ah[mt][1], ah[mt][2], ah[mt][3],
                                 bl[nt][0], bl[nt][1]);
                        mma16816(acc[mt][nt], al[mt][0], al[mt][1], al[mt][2], al[mt][3],
                                 bh[nt][0], bh[nt][1]);
                    }
            }
        }

        // store prefetched chunk into the other buffer
        if (c + 1 < nchunk) {
            char* st = smem + ((c + 1) & 1) * Cfg::SBUF;
            char* sAh = st;
            char* sAl = st + ATILE;
            char* sBh = st + 2 * ATILE;
            char* sBl = st + 2 * ATILE + Cfg::BTILE;
#pragma unroll
            for (int i = 0; i < 4; i++) {
                int f = tid + i * 256;
                int off = (f >> 3) * LDB + (f & 7) * 8;
                uint2 hp, lp;
                split_pack(pa[i], hp, lp);
                *reinterpret_cast<uint2*>(sAh + off) = hp;
                *reinterpret_cast<uint2*>(sAl + off) = lp;
            }
#pragma unroll
            for (int i = 0; i < PB; i++) {
                int f = tid + i * 256;
                int off = (f >> 3) * LDB + (f & 7) * 8;
                uint2 hp, lp;
                split_pack(pb[i], hp, lp);
                *reinterpret_cast<uint2*>(sBh + off) = hp;
                *reinterpret_cast<uint2*>(sBl + off) = lp;
            }
            __syncthreads();
        }
    }

    // ---- epilogue ----
    float* Cz = C + (size_t)blockIdx.z * sC;
    const float* Rz = R ? R + (size_t)blockIdx.z * sC : nullptr;
#pragma unroll
    for (int mt = 0; mt < 4; ++mt) {
        int row0 = blockIdx.y * GBM + wy * 64 + mt * 16 + (lane >> 2);
#pragma unroll
        for (int nt = 0; nt < NT; ++nt) {
            int col = blockIdx.x * BN + wx * Cfg::WTN + nt * 8 + (lane & 3) * 2;
            size_t o0 = (size_t)row0 * N + col;
            size_t o1 = (size_t)(row0 + 8) * N + col;
            float2 v0 = make_float2(acc[mt][nt][0], acc[mt][nt][1]);
            float2 v1 = make_float2(acc[mt][nt][2], acc[mt][nt][3]);
            if (Rz) {
                float2 r0 = *reinterpret_cast<const float2*>(Rz + o0);
                float2 r1 = *reinterpret_cast<const float2*>(Rz + o1);
                v0.x += r0.x; v0.y += r0.y;
                v1.x += r1.x; v1.y += r1.y;
            }
            *reinterpret_cast<float2*>(Cz + o0) = v0;
            *reinterpret_cast<float2*>(Cz + o1) = v1;
        }
    }
}

// ---------------- host ----------------
extern "C" void kernel_launch(void* const* d_in, const int* in_sizes, int n_in,
                              void* d_out, int out_size) {
    const int*   tokens       = (const int*)d_in[0];
    const float* embed        = (const float*)d_in[1];
    const float* attn_norm_w  = (const float*)d_in[2];
    const float* wq           = (const float*)d_in[3];
    const float* wk           = (const float*)d_in[4];
    const float* wv           = (const float*)d_in[5];
    const float* wo           = (const float*)d_in[6];
    const float* ffn_norm_w   = (const float*)d_in[7];
    const float* w1           = (const float*)d_in[8];
    const float* w2           = (const float*)d_in[9];
    const float* w3           = (const float*)d_in[10];
    const float* final_norm_w = (const float*)d_in[11];
    float* out = (float*)d_out;

    constexpr int SMEM128 = GemmCfg<128>::SMEM;  // 81920
    cudaFuncSetAttribute(gemm_mma_kernel<128>,
                         cudaFuncAttributeMaxDynamicSharedMemorySize, SMEM128);
    cudaFuncSetAttribute(flash_kernel,
                         cudaFuncAttributeMaxDynamicSharedMemorySize, FLASH_SMEM);

    float* buf = nullptr;
    cudaGetSymbolAddress((void**)&buf, g_buf);
    int* seg = nullptr;
    cudaGetSymbolAddress((void**)&seg, g_seg);

    float* x    = buf + OFF_X;
    float* y    = buf + OFF_Y;
    float* xn   = buf + OFF_XN;
    float* qr   = buf + OFF_Q;
    float* kr   = buf + OFF_K;
    float* vr   = buf + OFF_V;
    float* qp   = buf + OFF_QP;
    float* kp   = buf + OFF_KP;
    float* vt   = buf + OFF_VT;
    float* oc   = buf + OFF_OC;
    float* hf   = buf + OFF_HF;
    float* h1   = buf + OFF_H1;
    float* h3   = buf + OFF_H3;
    float* gg   = buf + OFF_G;
    float* ssum = buf + OFF_SSUM;
    float* scnt = buf + OFF_SCNT;
    float* cosT = buf + OFF_COS;
    float* sinT = buf + OFF_SIN;

    embed_kernel<<<BT, 128>>>(tokens, embed, x);
    rope_table_kernel<<<(SEQ * HALFHD + 255) / 256, 256>>>(cosT, sinT);

    for (int l = 0; l < NLAYER; l++) {
        const float* wq_l = wq + (size_t)l * DIM * DIM;
        const float* wk_l = wk + (size_t)l * DIM * DIM;
        const float* wv_l = wv + (size_t)l * DIM * DIM;
        const float* wo_l = wo + (size_t)l * DIM * DIM;
        const float* w1_l = w1 + (size_t)l * FFDIM * DIM;
        const float* w2_l = w2 + (size_t)l * DIM * FFDIM;
        const float* w3_l = w3 + (size_t)l * FFDIM * DIM;

        rmsnorm_kernel<<<BT, 128>>>(x, attn_norm_w + (size_t)l * DIM, xn);

        // QKV projections: [8192,512] = [8192,512] @ [512,512]^T
        dim3 gproj(DIM / 128, BT / 128, 1);
        gemm_mma_kernel<128><<<gproj, 256, SMEM128>>>(xn, wq_l, qr, nullptr, DIM, DIM, 0, 0, 0);
        gemm_mma_kernel<128><<<gproj, 256, SMEM128>>>(xn, wk_l, kr, nullptr, DIM, DIM, 0, 0, 0);
        gemm_mma_kernel<128><<<gproj, 256, SMEM128>>>(xn, wv_l, vr, nullptr, DIM, DIM, 0, 0, 0);

        pack_rope_kernel<<<(BSZ * NHEAD * SEQ * HALFHD + 255) / 256, 256>>>(
            qr, kr, cosT, sinT, qp, kp);
        vtrans_kernel<<<dim3(SEQ / 32, HDIM / 32, BSZ * NHEAD), dim3(32, 8)>>>(vr, vt);

        // fused attention: QK^T + online softmax + PV, O written to [B,T,512]
        flash_kernel<<<dim3(SEQ / 128, BSZ * NHEAD), 256, FLASH_SMEM>>>(qp, kp, vt, oc);

        // y = x + O @ Wo^T
        gemm_mma_kernel<128><<<gproj, 256, SMEM128>>>(oc, wo_l, y, x, DIM, DIM, 0, 0, 0);

        rmsnorm_kernel<<<BT, 128>>>(y, ffn_norm_w + (size_t)l * DIM, xn);

        dim3 gff(FFDIM / 128, BT / 128, 1);
        gemm_mma_kernel<128><<<gff, 256, SMEM128>>>(xn, w1_l, h1, nullptr, FFDIM, DIM, 0, 0, 0);
        gemm_mma_kernel<128><<<gff, 256, SMEM128>>>(xn, w3_l, h3, nullptr, FFDIM, DIM, 0, 0, 0);

        swiglu_kernel<<<(int)((NHID + 255) / 256), 256>>>(h1, h3, gg, NHID);

        // x = y + g @ W2^T   (K = 2048)
        gemm_mma_kernel<128><<<gproj, 256, SMEM128>>>(gg, w2_l, x, y, DIM, FFDIM, 0, 0, 0);
    }

    rmsnorm_kernel<<<BT, 128>>>(x, final_norm_w, hf);

    segscan_kernel<<<BSZ, 256>>>(tokens, seg);
    zero_kernel<<<4096, 256>>>(ssum, NSEGS + NSEGC);
    segsum_kernel<<<BT, 128>>>(hf, seg, ssum, scnt);
    pool_kernel<<<BT, 128>>>(hf, seg, ssum, scnt, out);
}